// round 2
// baseline (speedup 1.0000x reference)
#include <cuda_runtime.h>

#define NN 50000
#define EE 800000
#define HID 128
#define NLAYERS 4
#define NCLS 16
#define NGRAPH 512

// ---------------- device scratch (no allocation allowed) ----------------
__device__ float g_tmp [NN * HID];
__device__ float g_buf0[NN * HID];
__device__ float g_buf1[NN * HID];
__device__ float g_buf2[NN * HID];

__device__ int   g_cnt[NN];
__device__ int   g_rowptr[NN + 1];
__device__ int   g_cursor[NN];
__device__ int   g_col[EE];
__device__ float g_wgt[EE];
__device__ float g_dinv[NN];

__device__ float g_gsum[NGRAPH * HID];
__device__ int   g_gcnt[NGRAPH];

__device__ int   g_ei64;   // 1 if edge_index is int64, else int32
__device__ int   g_b64;    // 1 if batch is int64, else int32

// ---------------- dtype detection ----------------
// int64 array viewed as int32: odd words are high halves == 0 (values < 50000).
// int32 edge_index: odd words are random node ids -> not all zero.
// int32 batch: probe mid-array (graph id ~256) to dodge leading zeros.
__global__ void detect_kernel(const int* __restrict__ ei,
                              const int* __restrict__ batch) {
    if (threadIdx.x == 0 && blockIdx.x == 0) {
        int z = 1;
        for (int i = 1; i < 257; i += 2) if (ei[i] != 0) { z = 0; break; }
        g_ei64 = z;
        z = 1;
        for (int i = 25001; i < 25257; i += 2) if (batch[i] != 0) { z = 0; break; }
        g_b64 = z;
    }
}

__device__ __forceinline__ int load_idx(const void* p, long i, int is64) {
    return is64 ? (int)((const long long*)p)[i] : ((const int*)p)[i];
}

// ---------------- init / CSR build ----------------
__global__ void zero_kernel() {
    int i = blockIdx.x * blockDim.x + threadIdx.x;
    if (i < NGRAPH * HID) g_gsum[i] = 0.f;
    if (i < NGRAPH) g_gcnt[i] = 0;
    if (i < NN) g_cnt[i] = 0;
}

__global__ void hist_kernel(const void* __restrict__ ei) {
    int is64 = g_ei64;
    for (int e = blockIdx.x * blockDim.x + threadIdx.x; e < EE;
         e += gridDim.x * blockDim.x) {
        int d = load_idx(ei, (long)EE + e, is64);
        atomicAdd(&g_cnt[d], 1);
    }
}

__global__ void dinv_kernel() {
    int i = blockIdx.x * blockDim.x + threadIdx.x;
    if (i < NN) g_dinv[i] = rsqrtf((float)(g_cnt[i] + 1));
}

// single-block exclusive scan of g_cnt -> g_rowptr (and g_cursor copy)
__global__ void scan_kernel() {
    __shared__ int sh[1024];
    const int CH = (NN + 1023) / 1024;
    int tid = threadIdx.x;
    int base = tid * CH;
    int s = 0;
    for (int j = 0; j < CH; j++) {
        int i = base + j;
        if (i < NN) s += g_cnt[i];
    }
    sh[tid] = s;
    __syncthreads();
    for (int off = 1; off < 1024; off <<= 1) {
        int v = (tid >= off) ? sh[tid - off] : 0;
        __syncthreads();
        sh[tid] += v;
        __syncthreads();
    }
    int run = sh[tid] - s;  // exclusive prefix
    for (int j = 0; j < CH; j++) {
        int i = base + j;
        if (i < NN) {
            g_rowptr[i] = run;
            g_cursor[i] = run;
            run += g_cnt[i];
            if (i == NN - 1) g_rowptr[NN] = run;
        }
    }
}

__global__ void fill_kernel(const void* __restrict__ ei) {
    int is64 = g_ei64;
    for (int e = blockIdx.x * blockDim.x + threadIdx.x; e < EE;
         e += gridDim.x * blockDim.x) {
        int s = load_idx(ei, e, is64);
        int d = load_idx(ei, (long)EE + e, is64);
        int pos = atomicAdd(&g_cursor[d], 1);
        g_col[pos] = s;
        g_wgt[pos] = g_dinv[s] * g_dinv[d];
    }
}

// ---------------- GEMM: C[N,128] = (A1 (+A2)) @ W[128,128] ----------------
// BM=128, BN=128, BK=32, 256 threads, 8x8 micro-tile per thread.
__global__ __launch_bounds__(256) void gemm_kernel(
    const float* __restrict__ A1, const float* __restrict__ A2, int hasB,
    const float* __restrict__ W, float* __restrict__ C) {
    __shared__ float sA[32][129];   // transposed: sA[k][row], pad->conflict-free
    __shared__ float sW[32][128];   // sW[k][col]

    int tid = threadIdx.x;
    int tx = tid % 16;              // col group (8 cols)
    int ty = tid / 16;              // row group (8 rows)
    int rowBase = blockIdx.x * 128;

    int arow = tid / 8, acol = tid % 8;   // A loader
    int wrow = tid / 32, wc = tid % 32;   // W loader

    float acc[8][8];
#pragma unroll
    for (int r = 0; r < 8; r++)
#pragma unroll
        for (int c = 0; c < 8; c++) acc[r][c] = 0.f;

    for (int k0 = 0; k0 < 128; k0 += 32) {
#pragma unroll
        for (int i = 0; i < 4; i++) {
            int r = rowBase + arow + 32 * i;
            float4 v = make_float4(0.f, 0.f, 0.f, 0.f);
            if (r < NN) {
                v = *(const float4*)(A1 + (long)r * 128 + k0 + acol * 4);
                if (hasB) {
                    float4 u = *(const float4*)(A2 + (long)r * 128 + k0 + acol * 4);
                    v.x += u.x; v.y += u.y; v.z += u.z; v.w += u.w;
                }
            }
            sA[acol * 4 + 0][arow + 32 * i] = v.x;
            sA[acol * 4 + 1][arow + 32 * i] = v.y;
            sA[acol * 4 + 2][arow + 32 * i] = v.z;
            sA[acol * 4 + 3][arow + 32 * i] = v.w;
        }
#pragma unroll
        for (int i = 0; i < 4; i++) {
            float4 v = *(const float4*)(W + (long)(k0 + wrow + 8 * i) * 128 + wc * 4);
            *(float4*)&sW[wrow + 8 * i][wc * 4] = v;
        }
        __syncthreads();

#pragma unroll
        for (int kk = 0; kk < 32; kk++) {
            float a[8];
#pragma unroll
            for (int r = 0; r < 8; r++) a[r] = sA[kk][ty * 8 + r];
            float4 b0 = *(const float4*)&sW[kk][tx * 8];
            float4 b1 = *(const float4*)&sW[kk][tx * 8 + 4];
            float b[8] = {b0.x, b0.y, b0.z, b0.w, b1.x, b1.y, b1.z, b1.w};
#pragma unroll
            for (int r = 0; r < 8; r++)
#pragma unroll
                for (int c = 0; c < 8; c++)
                    acc[r][c] = fmaf(a[r], b[c], acc[r][c]);
        }
        __syncthreads();
    }

#pragma unroll
    for (int r = 0; r < 8; r++) {
        int row = rowBase + ty * 8 + r;
        if (row < NN) {
            float4 o0 = make_float4(acc[r][0], acc[r][1], acc[r][2], acc[r][3]);
            float4 o1 = make_float4(acc[r][4], acc[r][5], acc[r][6], acc[r][7]);
            *(float4*)(C + (long)row * 128 + tx * 8)     = o0;
            *(float4*)(C + (long)row * 128 + tx * 8 + 4) = o1;
        }
    }
}

// ---------------- aggregation: out = relu(sum_e w*tmp[src] + self + bias) --
__global__ __launch_bounds__(256) void agg_kernel(
    const float4* __restrict__ tmp, const float* __restrict__ bias,
    float4* __restrict__ out) {
    int lane = threadIdx.x & 31;
    int node = (blockIdx.x * blockDim.x + threadIdx.x) >> 5;
    if (node >= NN) return;

    int beg = g_rowptr[node];
    int end = g_rowptr[node + 1];

    float4 acc = make_float4(0.f, 0.f, 0.f, 0.f);
    int e = beg;
    for (; e + 2 <= end; e += 2) {
        int s0 = g_col[e];
        int s1 = g_col[e + 1];
        float w0 = g_wgt[e];
        float w1 = g_wgt[e + 1];
        float4 v0 = tmp[(long)s0 * 32 + lane];
        float4 v1 = tmp[(long)s1 * 32 + lane];
        acc.x = fmaf(w0, v0.x, acc.x); acc.y = fmaf(w0, v0.y, acc.y);
        acc.z = fmaf(w0, v0.z, acc.z); acc.w = fmaf(w0, v0.w, acc.w);
        acc.x = fmaf(w1, v1.x, acc.x); acc.y = fmaf(w1, v1.y, acc.y);
        acc.z = fmaf(w1, v1.z, acc.z); acc.w = fmaf(w1, v1.w, acc.w);
    }
    if (e < end) {
        int s0 = g_col[e];
        float w0 = g_wgt[e];
        float4 v0 = tmp[(long)s0 * 32 + lane];
        acc.x = fmaf(w0, v0.x, acc.x); acc.y = fmaf(w0, v0.y, acc.y);
        acc.z = fmaf(w0, v0.z, acc.z); acc.w = fmaf(w0, v0.w, acc.w);
    }
    // self loop: weight = dinv^2 = 1/deg
    float di = g_dinv[node];
    float ws = di * di;
    float4 v = tmp[(long)node * 32 + lane];
    acc.x = fmaf(ws, v.x, acc.x); acc.y = fmaf(ws, v.y, acc.y);
    acc.z = fmaf(ws, v.z, acc.z); acc.w = fmaf(ws, v.w, acc.w);

    float4 b = ((const float4*)bias)[lane];
    float4 o;
    o.x = fmaxf(acc.x + b.x, 0.f);
    o.y = fmaxf(acc.y + b.y, 0.f);
    o.z = fmaxf(acc.z + b.z, 0.f);
    o.w = fmaxf(acc.w + b.w, 0.f);
    out[(long)node * 32 + lane] = o;
}

// ---------------- pooling over sorted batch ids ----------------
#define POOL_NODES 256
__global__ void pool_kernel(const float* __restrict__ cur,
                            const void* __restrict__ batch) {
    int is64 = g_b64;
    int f = threadIdx.x;   // 128 threads = features
    int start = blockIdx.x * POOL_NODES;
    if (start >= NN) return;
    int endn = start + POOL_NODES;
    if (endn > NN) endn = NN;

    int curg = load_idx(batch, start, is64);
    float acc = 0.f;
    int cnt = 0;
    for (int nd = start; nd < endn; nd++) {
        int gg = load_idx(batch, nd, is64);
        if (gg != curg) {
            atomicAdd(&g_gsum[curg * HID + f], acc);
            if (f == 0) atomicAdd(&g_gcnt[curg], cnt);
            acc = 0.f; cnt = 0; curg = gg;
        }
        acc += cur[(long)nd * HID + f];
        cnt++;
    }
    atomicAdd(&g_gsum[curg * HID + f], acc);
    if (f == 0) atomicAdd(&g_gcnt[curg], cnt);
}

// ---------------- mean + linear head + write outputs ----------------
__global__ void final_kernel(const float* __restrict__ Wl,
                             const float* __restrict__ bl,
                             float* __restrict__ out) {
    __shared__ float sm[HID];
    int g = blockIdx.x;
    int f = threadIdx.x;
    float c = (float)g_gcnt[g];
    c = fmaxf(c, 1.f);
    float m = g_gsum[g * HID + f] / c;
    sm[f] = m;
    out[NGRAPH * NCLS + (long)g * HID + f] = m;  // global_mean after y
    __syncthreads();
    if (f < NCLS) {
        float y = bl[f];
#pragma unroll 8
        for (int k = 0; k < HID; k++) y = fmaf(sm[k], Wl[k * NCLS + f], y);
        out[g * NCLS + f] = y;
    }
}

// ---------------- host ----------------
extern "C" void kernel_launch(void* const* d_in, const int* in_sizes, int n_in,
                              void* d_out, int out_size) {
    const float* x     = (const float*)d_in[0];
    const void*  ei    = d_in[1];
    const void*  batch = d_in[2];
    const float* W_in  = (const float*)d_in[3];
    const float* b_in  = (const float*)d_in[4];
    const float* W_hid = (const float*)d_in[5];
    const float* b_hid = (const float*)d_in[6];
    const float* W_lin = (const float*)d_in[7];
    const float* b_lin = (const float*)d_in[8];
    float* out = (float*)d_out;

    float *tmp, *b0, *b1, *b2;
    cudaGetSymbolAddress((void**)&tmp, g_tmp);
    cudaGetSymbolAddress((void**)&b0, g_buf0);
    cudaGetSymbolAddress((void**)&b1, g_buf1);
    cudaGetSymbolAddress((void**)&b2, g_buf2);

    // dtype probe + CSR build
    detect_kernel<<<1, 32>>>((const int*)ei, (const int*)batch);
    zero_kernel<<<(NGRAPH * HID + 255) / 256, 256>>>();
    hist_kernel<<<1024, 256>>>(ei);
    dinv_kernel<<<(NN + 255) / 256, 256>>>();
    scan_kernel<<<1, 1024>>>();
    fill_kernel<<<1024, 256>>>(ei);

    const int GEMM_GRID = (NN + 127) / 128;
    const int AGG_GRID  = (NN * 32 + 255) / 256;

    // input layer: relu(gcn(x, W_in, b_in)) -> b0
    gemm_kernel<<<GEMM_GRID, 256>>>(x, x, 0, W_in, tmp);
    agg_kernel<<<AGG_GRID, 256>>>((const float4*)tmp, b_in, (float4*)b0);
    // layer 0: (b0 + 0) -> b1
    gemm_kernel<<<GEMM_GRID, 256>>>(b0, b0, 0, W_hid + 0 * 16384, tmp);
    agg_kernel<<<AGG_GRID, 256>>>((const float4*)tmp, b_hid + 0 * HID, (float4*)b1);
    // layer 1: (b1 + b0) -> b2
    gemm_kernel<<<GEMM_GRID, 256>>>(b1, b0, 1, W_hid + 1 * 16384, tmp);
    agg_kernel<<<AGG_GRID, 256>>>((const float4*)tmp, b_hid + 1 * HID, (float4*)b2);
    // layer 2: (b2 + b1) -> b0
    gemm_kernel<<<GEMM_GRID, 256>>>(b2, b1, 1, W_hid + 2 * 16384, tmp);
    agg_kernel<<<AGG_GRID, 256>>>((const float4*)tmp, b_hid + 2 * HID, (float4*)b0);
    // layer 3: (b0 + b2) -> b1
    gemm_kernel<<<GEMM_GRID, 256>>>(b0, b2, 1, W_hid + 3 * 16384, tmp);
    agg_kernel<<<AGG_GRID, 256>>>((const float4*)tmp, b_hid + 3 * HID, (float4*)b1);

    // pooling + head
    pool_kernel<<<(NN + POOL_NODES - 1) / POOL_NODES, 128>>>(b1, batch);
    final_kernel<<<NGRAPH, HID>>>(W_lin, b_lin, out);
}

// round 3
// speedup vs baseline: 1.0847x; 1.0847x over previous
#include <cuda_runtime.h>
#include <cuda_fp16.h>

#define NN 50000
#define EE 800000
#define HID 128
#define NLAYERS 4
#define NCLS 16
#define NGRAPH 512

// ---------------- device scratch (no allocation allowed) ----------------
__device__ __half g_tmph[NN * HID];     // fp16 GEMM output (gather source)
__device__ float  g_buf0[NN * HID];
__device__ float  g_buf1[NN * HID];
__device__ float  g_buf2[NN * HID];

__device__ int   g_cnt[NN];
__device__ int   g_rowptr[NN + 1];
__device__ int   g_cursor[NN];
__device__ int   g_col[EE];
__device__ float g_wgt[EE];
__device__ float g_dinv[NN];

__device__ float g_gsum[NGRAPH * HID];
__device__ int   g_gcnt[NGRAPH];

__device__ int   g_ei64;   // 1 if edge_index is int64, else int32
__device__ int   g_b64;    // 1 if batch is int64, else int32

// ---------------- dtype detection ----------------
__global__ void detect_kernel(const int* __restrict__ ei,
                              const int* __restrict__ batch) {
    if (threadIdx.x == 0 && blockIdx.x == 0) {
        int z = 1;
        for (int i = 1; i < 257; i += 2) if (ei[i] != 0) { z = 0; break; }
        g_ei64 = z;
        z = 1;
        for (int i = 25001; i < 25257; i += 2) if (batch[i] != 0) { z = 0; break; }
        g_b64 = z;
    }
}

__device__ __forceinline__ int load_idx(const void* p, long i, int is64) {
    return is64 ? (int)((const long long*)p)[i] : ((const int*)p)[i];
}

// ---------------- init / CSR build ----------------
__global__ void zero_kernel() {
    int i = blockIdx.x * blockDim.x + threadIdx.x;
    if (i < NGRAPH * HID) g_gsum[i] = 0.f;
    if (i < NGRAPH) g_gcnt[i] = 0;
    if (i < NN) g_cnt[i] = 0;
}

__global__ void hist_kernel(const void* __restrict__ ei) {
    int is64 = g_ei64;
    for (int e = blockIdx.x * blockDim.x + threadIdx.x; e < EE;
         e += gridDim.x * blockDim.x) {
        int d = load_idx(ei, (long)EE + e, is64);
        atomicAdd(&g_cnt[d], 1);
    }
}

// single-block exclusive scan of g_cnt -> g_rowptr/g_cursor, plus dinv
__global__ void scan_kernel() {
    __shared__ int sh[1024];
    const int CH = (NN + 1023) / 1024;
    int tid = threadIdx.x;
    int base = tid * CH;
    int s = 0;
    for (int j = 0; j < CH; j++) {
        int i = base + j;
        if (i < NN) {
            int c = g_cnt[i];
            s += c;
            g_dinv[i] = rsqrtf((float)(c + 1));
        }
    }
    sh[tid] = s;
    __syncthreads();
    for (int off = 1; off < 1024; off <<= 1) {
        int v = (tid >= off) ? sh[tid - off] : 0;
        __syncthreads();
        sh[tid] += v;
        __syncthreads();
    }
    int run = sh[tid] - s;  // exclusive prefix
    for (int j = 0; j < CH; j++) {
        int i = base + j;
        if (i < NN) {
            g_rowptr[i] = run;
            g_cursor[i] = run;
            run += g_cnt[i];
            if (i == NN - 1) g_rowptr[NN] = run;
        }
    }
}

__global__ void fill_kernel(const void* __restrict__ ei) {
    int is64 = g_ei64;
    for (int e = blockIdx.x * blockDim.x + threadIdx.x; e < EE;
         e += gridDim.x * blockDim.x) {
        int s = load_idx(ei, e, is64);
        int d = load_idx(ei, (long)EE + e, is64);
        int pos = atomicAdd(&g_cursor[d], 1);
        g_col[pos] = s;
        g_wgt[pos] = g_dinv[s] * g_dinv[d];
    }
}

// ---------------- GEMM: Ch[N,128](fp16) = (A1 (+A2)) @ W[128,128] ---------
// BM=128, BN=128, BK=32, 256 threads, 8x8 micro-tile per thread.
__global__ __launch_bounds__(256) void gemm_kernel(
    const float* __restrict__ A1, const float* __restrict__ A2, int hasB,
    const float* __restrict__ W, __half* __restrict__ Ch) {
    __shared__ float sA[32][129];   // transposed: sA[k][row]
    __shared__ float sW[32][128];   // sW[k][col]

    int tid = threadIdx.x;
    int tx = tid % 16;              // col group (8 cols)
    int ty = tid / 16;              // row group (8 rows)
    int rowBase = blockIdx.x * 128;

    int arow = tid / 8, acol = tid % 8;   // A loader
    int wrow = tid / 32, wc = tid % 32;   // W loader

    float acc[8][8];
#pragma unroll
    for (int r = 0; r < 8; r++)
#pragma unroll
        for (int c = 0; c < 8; c++) acc[r][c] = 0.f;

    for (int k0 = 0; k0 < 128; k0 += 32) {
#pragma unroll
        for (int i = 0; i < 4; i++) {
            int r = rowBase + arow + 32 * i;
            float4 v = make_float4(0.f, 0.f, 0.f, 0.f);
            if (r < NN) {
                v = *(const float4*)(A1 + (long)r * 128 + k0 + acol * 4);
                if (hasB) {
                    float4 u = *(const float4*)(A2 + (long)r * 128 + k0 + acol * 4);
                    v.x += u.x; v.y += u.y; v.z += u.z; v.w += u.w;
                }
            }
            sA[acol * 4 + 0][arow + 32 * i] = v.x;
            sA[acol * 4 + 1][arow + 32 * i] = v.y;
            sA[acol * 4 + 2][arow + 32 * i] = v.z;
            sA[acol * 4 + 3][arow + 32 * i] = v.w;
        }
#pragma unroll
        for (int i = 0; i < 4; i++) {
            float4 v = *(const float4*)(W + (long)(k0 + wrow + 8 * i) * 128 + wc * 4);
            *(float4*)&sW[wrow + 8 * i][wc * 4] = v;
        }
        __syncthreads();

#pragma unroll
        for (int kk = 0; kk < 32; kk++) {
            float a[8];
#pragma unroll
            for (int r = 0; r < 8; r++) a[r] = sA[kk][ty * 8 + r];
            float4 b0 = *(const float4*)&sW[kk][tx * 8];
            float4 b1 = *(const float4*)&sW[kk][tx * 8 + 4];
            float b[8] = {b0.x, b0.y, b0.z, b0.w, b1.x, b1.y, b1.z, b1.w};
#pragma unroll
            for (int r = 0; r < 8; r++)
#pragma unroll
                for (int c = 0; c < 8; c++)
                    acc[r][c] = fmaf(a[r], b[c], acc[r][c]);
        }
        __syncthreads();
    }

#pragma unroll
    for (int r = 0; r < 8; r++) {
        int row = rowBase + ty * 8 + r;
        if (row < NN) {
            __half2 h[4];
            h[0] = __floats2half2_rn(acc[r][0], acc[r][1]);
            h[1] = __floats2half2_rn(acc[r][2], acc[r][3]);
            h[2] = __floats2half2_rn(acc[r][4], acc[r][5]);
            h[3] = __floats2half2_rn(acc[r][6], acc[r][7]);
            *(uint4*)(Ch + (long)row * 128 + tx * 8) = *(uint4*)h;
        }
    }
}

// ---------------- aggregation: out = relu(sum_e w*tmp[src] + self + bias) --
// warp per node, lane covers 4 features (fp16 gather, fp32 accumulate)
__device__ __forceinline__ void fma_h(float4& acc, float w, uint2 v) {
    __half2 h0 = *(__half2*)&v.x;
    __half2 h1 = *(__half2*)&v.y;
    float2 f0 = __half22float2(h0);
    float2 f1 = __half22float2(h1);
    acc.x = fmaf(w, f0.x, acc.x); acc.y = fmaf(w, f0.y, acc.y);
    acc.z = fmaf(w, f1.x, acc.z); acc.w = fmaf(w, f1.y, acc.w);
}

__global__ __launch_bounds__(256) void agg_kernel(
    const uint2* __restrict__ tmp, const float* __restrict__ bias,
    float4* __restrict__ out) {
    int lane = threadIdx.x & 31;
    int node = (blockIdx.x * blockDim.x + threadIdx.x) >> 5;
    if (node >= NN) return;

    int beg = g_rowptr[node];
    int end = g_rowptr[node + 1];

    float4 acc = make_float4(0.f, 0.f, 0.f, 0.f);
    int e = beg;
    for (; e + 4 <= end; e += 4) {
        int s0 = g_col[e],     s1 = g_col[e + 1];
        int s2 = g_col[e + 2], s3 = g_col[e + 3];
        float w0 = g_wgt[e],     w1 = g_wgt[e + 1];
        float w2 = g_wgt[e + 2], w3 = g_wgt[e + 3];
        uint2 v0 = tmp[(long)s0 * 32 + lane];
        uint2 v1 = tmp[(long)s1 * 32 + lane];
        uint2 v2 = tmp[(long)s2 * 32 + lane];
        uint2 v3 = tmp[(long)s3 * 32 + lane];
        fma_h(acc, w0, v0); fma_h(acc, w1, v1);
        fma_h(acc, w2, v2); fma_h(acc, w3, v3);
    }
    for (; e < end; e++) {
        int s0 = g_col[e];
        float w0 = g_wgt[e];
        uint2 v0 = tmp[(long)s0 * 32 + lane];
        fma_h(acc, w0, v0);
    }
    // self loop: weight = dinv^2 = 1/deg
    float di = g_dinv[node];
    uint2 v = tmp[(long)node * 32 + lane];
    fma_h(acc, di * di, v);

    float4 b = ((const float4*)bias)[lane];
    float4 o;
    o.x = fmaxf(acc.x + b.x, 0.f);
    o.y = fmaxf(acc.y + b.y, 0.f);
    o.z = fmaxf(acc.z + b.z, 0.f);
    o.w = fmaxf(acc.w + b.w, 0.f);
    out[(long)node * 32 + lane] = o;
}

// ---------------- pooling over sorted batch ids ----------------
#define POOL_NODES 256
__global__ void pool_kernel(const float* __restrict__ cur,
                            const void* __restrict__ batch) {
    int is64 = g_b64;
    int f = threadIdx.x;   // 128 threads = features
    int start = blockIdx.x * POOL_NODES;
    if (start >= NN) return;
    int endn = start + POOL_NODES;
    if (endn > NN) endn = NN;

    int curg = load_idx(batch, start, is64);
    float acc = 0.f;
    int cnt = 0;
    for (int nd = start; nd < endn; nd++) {
        int gg = load_idx(batch, nd, is64);
        if (gg != curg) {
            atomicAdd(&g_gsum[curg * HID + f], acc);
            if (f == 0) atomicAdd(&g_gcnt[curg], cnt);
            acc = 0.f; cnt = 0; curg = gg;
        }
        acc += cur[(long)nd * HID + f];
        cnt++;
    }
    atomicAdd(&g_gsum[curg * HID + f], acc);
    if (f == 0) atomicAdd(&g_gcnt[curg], cnt);
}

// ---------------- mean + linear head + write outputs ----------------
__global__ void final_kernel(const float* __restrict__ Wl,
                             const float* __restrict__ bl,
                             float* __restrict__ out) {
    __shared__ float sm[HID];
    int g = blockIdx.x;
    int f = threadIdx.x;
    float c = (float)g_gcnt[g];
    c = fmaxf(c, 1.f);
    float m = g_gsum[g * HID + f] / c;
    sm[f] = m;
    out[NGRAPH * NCLS + (long)g * HID + f] = m;  // global_mean after y
    __syncthreads();
    if (f < NCLS) {
        float y = bl[f];
#pragma unroll 8
        for (int k = 0; k < HID; k++) y = fmaf(sm[k], Wl[k * NCLS + f], y);
        out[g * NCLS + f] = y;
    }
}

// ---------------- host ----------------
extern "C" void kernel_launch(void* const* d_in, const int* in_sizes, int n_in,
                              void* d_out, int out_size) {
    const float* x     = (const float*)d_in[0];
    const void*  ei    = d_in[1];
    const void*  batch = d_in[2];
    const float* W_in  = (const float*)d_in[3];
    const float* b_in  = (const float*)d_in[4];
    const float* W_hid = (const float*)d_in[5];
    const float* b_hid = (const float*)d_in[6];
    const float* W_lin = (const float*)d_in[7];
    const float* b_lin = (const float*)d_in[8];
    float* out = (float*)d_out;

    __half* tmph;
    float *b0, *b1, *b2;
    cudaGetSymbolAddress((void**)&tmph, g_tmph);
    cudaGetSymbolAddress((void**)&b0, g_buf0);
    cudaGetSymbolAddress((void**)&b1, g_buf1);
    cudaGetSymbolAddress((void**)&b2, g_buf2);

    // dtype probe + CSR build
    detect_kernel<<<1, 32>>>((const int*)ei, (const int*)batch);
    zero_kernel<<<(NGRAPH * HID + 255) / 256, 256>>>();
    hist_kernel<<<1024, 256>>>(ei);
    scan_kernel<<<1, 1024>>>();
    fill_kernel<<<1024, 256>>>(ei);

    const int GEMM_GRID = (NN + 127) / 128;
    const int AGG_GRID  = (NN * 32 + 255) / 256;

    // input layer: relu(gcn(x, W_in, b_in)) -> b0
    gemm_kernel<<<GEMM_GRID, 256>>>(x, x, 0, W_in, tmph);
    agg_kernel<<<AGG_GRID, 256>>>((const uint2*)tmph, b_in, (float4*)b0);
    // layer 0: (b0 + 0) -> b1
    gemm_kernel<<<GEMM_GRID, 256>>>(b0, b0, 0, W_hid + 0 * 16384, tmph);
    agg_kernel<<<AGG_GRID, 256>>>((const uint2*)tmph, b_hid + 0 * HID, (float4*)b1);
    // layer 1: (b1 + b0) -> b2
    gemm_kernel<<<GEMM_GRID, 256>>>(b1, b0, 1, W_hid + 1 * 16384, tmph);
    agg_kernel<<<AGG_GRID, 256>>>((const uint2*)tmph, b_hid + 1 * HID, (float4*)b2);
    // layer 2: (b2 + b1) -> b0
    gemm_kernel<<<GEMM_GRID, 256>>>(b2, b1, 1, W_hid + 2 * 16384, tmph);
    agg_kernel<<<AGG_GRID, 256>>>((const uint2*)tmph, b_hid + 2 * HID, (float4*)b0);
    // layer 3: (b0 + b2) -> b1
    gemm_kernel<<<GEMM_GRID, 256>>>(b0, b2, 1, W_hid + 3 * 16384, tmph);
    agg_kernel<<<AGG_GRID, 256>>>((const uint2*)tmph, b_hid + 3 * HID, (float4*)b1);

    // pooling + head
    pool_kernel<<<(NN + POOL_NODES - 1) / POOL_NODES, 128>>>(b1, batch);
    final_kernel<<<NGRAPH, HID>>>(W_lin, b_lin, out);
}

// round 4
// speedup vs baseline: 1.4152x; 1.3047x over previous
#include <cuda_runtime.h>
#include <cuda_fp16.h>

#define NN 50000
#define EE 800000
#define HID 128
#define NCLS 16
#define NGRAPH 512

#define SCAN_TPB 256
#define SCAN_NB ((NN + SCAN_TPB - 1) / SCAN_TPB)   // 196

// ---------------- device scratch (no allocation allowed) ----------------
__device__ __half g_tmph[NN * HID];     // fp16 dinv-scaled GEMM output
__device__ float  g_buf0[NN * HID];
__device__ float  g_buf1[NN * HID];
__device__ float  g_buf2[NN * HID];

__device__ int   g_cnt[NN];
__device__ int   g_rowptr[NN + 1];
__device__ int   g_cursor[NN];
__device__ int   g_col[EE];
__device__ float g_dinv[NN];
__device__ int   g_bsum[SCAN_NB];

__device__ float g_gsum[NGRAPH * HID];
__device__ int   g_gcnt[NGRAPH];

__device__ int   g_ei64;   // 1 if edge_index is int64, else int32
__device__ int   g_b64;    // 1 if batch is int64, else int32

// ---------------- dtype detection ----------------
__global__ void detect_kernel(const int* __restrict__ ei,
                              const int* __restrict__ batch) {
    if (threadIdx.x == 0 && blockIdx.x == 0) {
        int z = 1;
        for (int i = 1; i < 257; i += 2) if (ei[i] != 0) { z = 0; break; }
        g_ei64 = z;
        z = 1;
        for (int i = 25001; i < 25257; i += 2) if (batch[i] != 0) { z = 0; break; }
        g_b64 = z;
    }
}

__device__ __forceinline__ int load_idx(const void* p, long i, int is64) {
    return is64 ? (int)((const long long*)p)[i] : ((const int*)p)[i];
}

// ---------------- init / CSR build ----------------
__global__ void zero_kernel() {
    int i = blockIdx.x * blockDim.x + threadIdx.x;
    if (i < NGRAPH * HID) g_gsum[i] = 0.f;
    if (i < NGRAPH) g_gcnt[i] = 0;
    if (i < NN) g_cnt[i] = 0;
}

__global__ void hist_kernel(const void* __restrict__ ei) {
    int is64 = g_ei64;
    for (int e = blockIdx.x * blockDim.x + threadIdx.x; e < EE;
         e += gridDim.x * blockDim.x) {
        int d = load_idx(ei, (long)EE + e, is64);
        atomicAdd(&g_cnt[d], 1);
    }
}

// phase 1: per-block inclusive scan, write local-exclusive + block total + dinv
__global__ __launch_bounds__(SCAN_TPB) void scan1_kernel() {
    __shared__ int sh[SCAN_TPB];
    int tid = threadIdx.x;
    int i = blockIdx.x * SCAN_TPB + tid;
    int c = (i < NN) ? g_cnt[i] : 0;
    if (i < NN) g_dinv[i] = rsqrtf((float)(c + 1));
    sh[tid] = c;
    __syncthreads();
#pragma unroll
    for (int off = 1; off < SCAN_TPB; off <<= 1) {
        int v = (tid >= off) ? sh[tid - off] : 0;
        __syncthreads();
        sh[tid] += v;
        __syncthreads();
    }
    if (i < NN) g_rowptr[i] = sh[tid] - c;     // local exclusive
    if (tid == SCAN_TPB - 1) g_bsum[blockIdx.x] = sh[tid];
}

// phase 2: scan the 196 block sums (single tiny block)
__global__ __launch_bounds__(SCAN_TPB) void scan2_kernel() {
    __shared__ int sh[SCAN_TPB];
    int tid = threadIdx.x;
    int c = (tid < SCAN_NB) ? g_bsum[tid] : 0;
    sh[tid] = c;
    __syncthreads();
#pragma unroll
    for (int off = 1; off < SCAN_TPB; off <<= 1) {
        int v = (tid >= off) ? sh[tid - off] : 0;
        __syncthreads();
        sh[tid] += v;
        __syncthreads();
    }
    if (tid < SCAN_NB) g_bsum[tid] = sh[tid] - c;   // exclusive
}

// phase 3: add block offsets, init cursor, rowptr[NN]
__global__ __launch_bounds__(SCAN_TPB) void scan3_kernel() {
    int i = blockIdx.x * SCAN_TPB + threadIdx.x;
    if (i < NN) {
        int v = g_rowptr[i] + g_bsum[blockIdx.x];
        g_rowptr[i] = v;
        g_cursor[i] = v;
    }
    if (i == 0) g_rowptr[NN] = EE;
}

__global__ void fill_kernel(const void* __restrict__ ei) {
    int is64 = g_ei64;
    for (int e = blockIdx.x * blockDim.x + threadIdx.x; e < EE;
         e += gridDim.x * blockDim.x) {
        int s = load_idx(ei, e, is64);
        int d = load_idx(ei, (long)EE + e, is64);
        int pos = atomicAdd(&g_cursor[d], 1);
        g_col[pos] = s;
    }
}

// ---------------- GEMM: Ch[N,128](fp16) = dinv[row]*((A1 (+A2)) @ W) ------
// BM=128, BN=128, BK=32, 256 threads, 8x8 micro-tile per thread.
__global__ __launch_bounds__(256) void gemm_kernel(
    const float* __restrict__ A1, const float* __restrict__ A2, int hasB,
    const float* __restrict__ W, __half* __restrict__ Ch) {
    __shared__ float sA[32][129];   // transposed: sA[k][row]
    __shared__ float sW[32][128];   // sW[k][col]

    int tid = threadIdx.x;
    int tx = tid % 16;              // col group (8 cols)
    int ty = tid / 16;              // row group (8 rows)
    int rowBase = blockIdx.x * 128;

    int arow = tid / 8, acol = tid % 8;   // A loader
    int wrow = tid / 32, wc = tid % 32;   // W loader

    float acc[8][8];
#pragma unroll
    for (int r = 0; r < 8; r++)
#pragma unroll
        for (int c = 0; c < 8; c++) acc[r][c] = 0.f;

    for (int k0 = 0; k0 < 128; k0 += 32) {
#pragma unroll
        for (int i = 0; i < 4; i++) {
            int r = rowBase + arow + 32 * i;
            float4 v = make_float4(0.f, 0.f, 0.f, 0.f);
            if (r < NN) {
                v = *(const float4*)(A1 + (long)r * 128 + k0 + acol * 4);
                if (hasB) {
                    float4 u = *(const float4*)(A2 + (long)r * 128 + k0 + acol * 4);
                    v.x += u.x; v.y += u.y; v.z += u.z; v.w += u.w;
                }
            }
            sA[acol * 4 + 0][arow + 32 * i] = v.x;
            sA[acol * 4 + 1][arow + 32 * i] = v.y;
            sA[acol * 4 + 2][arow + 32 * i] = v.z;
            sA[acol * 4 + 3][arow + 32 * i] = v.w;
        }
#pragma unroll
        for (int i = 0; i < 4; i++) {
            float4 v = *(const float4*)(W + (long)(k0 + wrow + 8 * i) * 128 + wc * 4);
            *(float4*)&sW[wrow + 8 * i][wc * 4] = v;
        }
        __syncthreads();

#pragma unroll
        for (int kk = 0; kk < 32; kk++) {
            float a[8];
#pragma unroll
            for (int r = 0; r < 8; r++) a[r] = sA[kk][ty * 8 + r];
            float4 b0 = *(const float4*)&sW[kk][tx * 8];
            float4 b1 = *(const float4*)&sW[kk][tx * 8 + 4];
            float b[8] = {b0.x, b0.y, b0.z, b0.w, b1.x, b1.y, b1.z, b1.w};
#pragma unroll
            for (int r = 0; r < 8; r++)
#pragma unroll
                for (int c = 0; c < 8; c++)
                    acc[r][c] = fmaf(a[r], b[c], acc[r][c]);
        }
        __syncthreads();
    }

#pragma unroll
    for (int r = 0; r < 8; r++) {
        int row = rowBase + ty * 8 + r;
        if (row < NN) {
            float di = g_dinv[row];
            __half2 h[4];
            h[0] = __floats2half2_rn(di * acc[r][0], di * acc[r][1]);
            h[1] = __floats2half2_rn(di * acc[r][2], di * acc[r][3]);
            h[2] = __floats2half2_rn(di * acc[r][4], di * acc[r][5]);
            h[3] = __floats2half2_rn(di * acc[r][6], di * acc[r][7]);
            *(uint4*)(Ch + (long)row * 128 + tx * 8) = *(uint4*)h;
        }
    }
}

// ---------------- aggregation: out = relu(dinv[d]*(sum tmp'[src] + tmp'[d]) + b)
__device__ __forceinline__ void add_h(float4& acc, uint2 v) {
    __half2 h0 = *(__half2*)&v.x;
    __half2 h1 = *(__half2*)&v.y;
    float2 f0 = __half22float2(h0);
    float2 f1 = __half22float2(h1);
    acc.x += f0.x; acc.y += f0.y; acc.z += f1.x; acc.w += f1.y;
}

__global__ __launch_bounds__(256) void agg_kernel(
    const uint2* __restrict__ tmp, const float* __restrict__ bias,
    float4* __restrict__ out) {
    int lane = threadIdx.x & 31;
    int node = (blockIdx.x * blockDim.x + threadIdx.x) >> 5;
    if (node >= NN) return;

    int beg = g_rowptr[node];
    int end = g_rowptr[node + 1];

    float4 acc = make_float4(0.f, 0.f, 0.f, 0.f);
    int e = beg;
    for (; e + 8 <= end; e += 8) {
        uint2 v0 = tmp[(long)g_col[e    ] * 32 + lane];
        uint2 v1 = tmp[(long)g_col[e + 1] * 32 + lane];
        uint2 v2 = tmp[(long)g_col[e + 2] * 32 + lane];
        uint2 v3 = tmp[(long)g_col[e + 3] * 32 + lane];
        uint2 v4 = tmp[(long)g_col[e + 4] * 32 + lane];
        uint2 v5 = tmp[(long)g_col[e + 5] * 32 + lane];
        uint2 v6 = tmp[(long)g_col[e + 6] * 32 + lane];
        uint2 v7 = tmp[(long)g_col[e + 7] * 32 + lane];
        add_h(acc, v0); add_h(acc, v1); add_h(acc, v2); add_h(acc, v3);
        add_h(acc, v4); add_h(acc, v5); add_h(acc, v6); add_h(acc, v7);
    }
    for (; e < end; e++) {
        uint2 v0 = tmp[(long)g_col[e] * 32 + lane];
        add_h(acc, v0);
    }
    // self loop contribution
    uint2 vs = tmp[(long)node * 32 + lane];
    add_h(acc, vs);

    float di = g_dinv[node];
    float4 b = ((const float4*)bias)[lane];
    float4 o;
    o.x = fmaxf(fmaf(di, acc.x, b.x), 0.f);
    o.y = fmaxf(fmaf(di, acc.y, b.y), 0.f);
    o.z = fmaxf(fmaf(di, acc.z, b.z), 0.f);
    o.w = fmaxf(fmaf(di, acc.w, b.w), 0.f);
    out[(long)node * 32 + lane] = o;
}

// ---------------- pooling over sorted batch ids ----------------
#define POOL_NODES 256
__global__ void pool_kernel(const float* __restrict__ cur,
                            const void* __restrict__ batch) {
    int is64 = g_b64;
    int f = threadIdx.x;   // 128 threads = features
    int start = blockIdx.x * POOL_NODES;
    if (start >= NN) return;
    int endn = start + POOL_NODES;
    if (endn > NN) endn = NN;

    int curg = load_idx(batch, start, is64);
    float acc = 0.f;
    int cnt = 0;
    for (int nd = start; nd < endn; nd++) {
        int gg = load_idx(batch, nd, is64);
        if (gg != curg) {
            atomicAdd(&g_gsum[curg * HID + f], acc);
            if (f == 0) atomicAdd(&g_gcnt[curg], cnt);
            acc = 0.f; cnt = 0; curg = gg;
        }
        acc += cur[(long)nd * HID + f];
        cnt++;
    }
    atomicAdd(&g_gsum[curg * HID + f], acc);
    if (f == 0) atomicAdd(&g_gcnt[curg], cnt);
}

// ---------------- mean + linear head + write outputs ----------------
__global__ void final_kernel(const float* __restrict__ Wl,
                             const float* __restrict__ bl,
                             float* __restrict__ out) {
    __shared__ float sm[HID];
    int g = blockIdx.x;
    int f = threadIdx.x;
    float c = (float)g_gcnt[g];
    c = fmaxf(c, 1.f);
    float m = g_gsum[g * HID + f] / c;
    sm[f] = m;
    out[NGRAPH * NCLS + (long)g * HID + f] = m;  // global_mean after y
    __syncthreads();
    if (f < NCLS) {
        float y = bl[f];
#pragma unroll 8
        for (int k = 0; k < HID; k++) y = fmaf(sm[k], Wl[k * NCLS + f], y);
        out[g * NCLS + f] = y;
    }
}

// ---------------- host ----------------
extern "C" void kernel_launch(void* const* d_in, const int* in_sizes, int n_in,
                              void* d_out, int out_size) {
    const float* x     = (const float*)d_in[0];
    const void*  ei    = d_in[1];
    const void*  batch = d_in[2];
    const float* W_in  = (const float*)d_in[3];
    const float* b_in  = (const float*)d_in[4];
    const float* W_hid = (const float*)d_in[5];
    const float* b_hid = (const float*)d_in[6];
    const float* W_lin = (const float*)d_in[7];
    const float* b_lin = (const float*)d_in[8];
    float* out = (float*)d_out;

    __half* tmph;
    float *b0, *b1, *b2;
    cudaGetSymbolAddress((void**)&tmph, g_tmph);
    cudaGetSymbolAddress((void**)&b0, g_buf0);
    cudaGetSymbolAddress((void**)&b1, g_buf1);
    cudaGetSymbolAddress((void**)&b2, g_buf2);

    // dtype probe + CSR build
    detect_kernel<<<1, 32>>>((const int*)ei, (const int*)batch);
    zero_kernel<<<(NGRAPH * HID + 255) / 256, 256>>>();
    hist_kernel<<<1024, 256>>>(ei);
    scan1_kernel<<<SCAN_NB, SCAN_TPB>>>();
    scan2_kernel<<<1, SCAN_TPB>>>();
    scan3_kernel<<<SCAN_NB, SCAN_TPB>>>();
    fill_kernel<<<1024, 256>>>(ei);

    const int GEMM_GRID = (NN + 127) / 128;
    const int AGG_GRID  = (NN * 32 + 255) / 256;

    // input layer: relu(gcn(x, W_in, b_in)) -> b0
    gemm_kernel<<<GEMM_GRID, 256>>>(x, x, 0, W_in, tmph);
    agg_kernel<<<AGG_GRID, 256>>>((const uint2*)tmph, b_in, (float4*)b0);
    // layer 0: (b0 + 0) -> b1
    gemm_kernel<<<GEMM_GRID, 256>>>(b0, b0, 0, W_hid + 0 * 16384, tmph);
    agg_kernel<<<AGG_GRID, 256>>>((const uint2*)tmph, b_hid + 0 * HID, (float4*)b1);
    // layer 1: (b1 + b0) -> b2
    gemm_kernel<<<GEMM_GRID, 256>>>(b1, b0, 1, W_hid + 1 * 16384, tmph);
    agg_kernel<<<AGG_GRID, 256>>>((const uint2*)tmph, b_hid + 1 * HID, (float4*)b2);
    // layer 2: (b2 + b1) -> b0
    gemm_kernel<<<GEMM_GRID, 256>>>(b2, b1, 1, W_hid + 2 * 16384, tmph);
    agg_kernel<<<AGG_GRID, 256>>>((const uint2*)tmph, b_hid + 2 * HID, (float4*)b0);
    // layer 3: (b0 + b2) -> b1
    gemm_kernel<<<GEMM_GRID, 256>>>(b0, b2, 1, W_hid + 3 * 16384, tmph);
    agg_kernel<<<AGG_GRID, 256>>>((const uint2*)tmph, b_hid + 3 * HID, (float4*)b1);

    // pooling + head
    pool_kernel<<<(NN + POOL_NODES - 1) / POOL_NODES, 128>>>(b1, batch);
    final_kernel<<<NGRAPH, HID>>>(W_lin, b_lin, out);
}

// round 5
// speedup vs baseline: 2.0631x; 1.4577x over previous
#include <cuda_runtime.h>
#include <cuda_fp16.h>

#define NN 50000
#define EE 800000
#define HID 128
#define NCLS 16
#define NGRAPH 512

#define SCAN_TPB 256
#define SCAN_NB ((NN + SCAN_TPB - 1) / SCAN_TPB)   // 196

// ---------------- device scratch (no allocation allowed) ----------------
__device__ __half g_tmph[NN * HID];     // fp16 dinv-scaled GEMM output
__device__ __half g_xh  [NN * HID];     // fp16 copy of input x
__device__ __half g_hb0 [NN * HID];
__device__ __half g_hb1 [NN * HID];
__device__ __half g_hb2 [NN * HID];

__device__ int   g_cnt[NN];
__device__ int   g_rowptr[NN + 1];
__device__ int   g_cursor[NN];
__device__ int   g_col[EE];
__device__ float g_dinv[NN];
__device__ int   g_bsum[SCAN_NB];

__device__ float g_gsum[NGRAPH * HID];
__device__ int   g_gcnt[NGRAPH];

__device__ int   g_ei64;
__device__ int   g_b64;

// ---------------- dtype detection ----------------
__global__ void detect_kernel(const int* __restrict__ ei,
                              const int* __restrict__ batch) {
    if (threadIdx.x == 0 && blockIdx.x == 0) {
        int z = 1;
        for (int i = 1; i < 257; i += 2) if (ei[i] != 0) { z = 0; break; }
        g_ei64 = z;
        z = 1;
        for (int i = 25001; i < 25257; i += 2) if (batch[i] != 0) { z = 0; break; }
        g_b64 = z;
    }
}

__device__ __forceinline__ int load_idx(const void* p, long i, int is64) {
    return is64 ? (int)((const long long*)p)[i] : ((const int*)p)[i];
}

// ---------------- init / CSR build ----------------
__global__ void zero_kernel() {
    int i = blockIdx.x * blockDim.x + threadIdx.x;
    if (i < NGRAPH * HID) g_gsum[i] = 0.f;
    if (i < NGRAPH) g_gcnt[i] = 0;
    if (i < NN) g_cnt[i] = 0;
}

__global__ void hist_kernel(const void* __restrict__ ei) {
    int is64 = g_ei64;
    for (int e = blockIdx.x * blockDim.x + threadIdx.x; e < EE;
         e += gridDim.x * blockDim.x) {
        int d = load_idx(ei, (long)EE + e, is64);
        atomicAdd(&g_cnt[d], 1);
    }
}

__global__ __launch_bounds__(SCAN_TPB) void scan1_kernel() {
    __shared__ int sh[SCAN_TPB];
    int tid = threadIdx.x;
    int i = blockIdx.x * SCAN_TPB + tid;
    int c = (i < NN) ? g_cnt[i] : 0;
    if (i < NN) g_dinv[i] = rsqrtf((float)(c + 1));
    sh[tid] = c;
    __syncthreads();
#pragma unroll
    for (int off = 1; off < SCAN_TPB; off <<= 1) {
        int v = (tid >= off) ? sh[tid - off] : 0;
        __syncthreads();
        sh[tid] += v;
        __syncthreads();
    }
    if (i < NN) g_rowptr[i] = sh[tid] - c;
    if (tid == SCAN_TPB - 1) g_bsum[blockIdx.x] = sh[tid];
}

__global__ __launch_bounds__(SCAN_TPB) void scan2_kernel() {
    __shared__ int sh[SCAN_TPB];
    int tid = threadIdx.x;
    int c = (tid < SCAN_NB) ? g_bsum[tid] : 0;
    sh[tid] = c;
    __syncthreads();
#pragma unroll
    for (int off = 1; off < SCAN_TPB; off <<= 1) {
        int v = (tid >= off) ? sh[tid - off] : 0;
        __syncthreads();
        sh[tid] += v;
        __syncthreads();
    }
    if (tid < SCAN_NB) g_bsum[tid] = sh[tid] - c;
}

__global__ __launch_bounds__(SCAN_TPB) void scan3_kernel() {
    int i = blockIdx.x * SCAN_TPB + threadIdx.x;
    if (i < NN) {
        int v = g_rowptr[i] + g_bsum[blockIdx.x];
        g_rowptr[i] = v;
        g_cursor[i] = v;
    }
    if (i == 0) g_rowptr[NN] = EE;
}

__global__ void fill_kernel(const void* __restrict__ ei) {
    int is64 = g_ei64;
    for (int e = blockIdx.x * blockDim.x + threadIdx.x; e < EE;
         e += gridDim.x * blockDim.x) {
        int s = load_idx(ei, e, is64);
        int d = load_idx(ei, (long)EE + e, is64);
        int pos = atomicAdd(&g_cursor[d], 1);
        g_col[pos] = s;
    }
}

// ---------------- fp32 -> fp16 convert of x ----------------
__global__ void cvt_kernel(const float4* __restrict__ x, uint2* __restrict__ xh) {
    int i = blockIdx.x * blockDim.x + threadIdx.x;
    if (i < NN * 32) {
        float4 v = x[i];
        __half2 h0 = __floats2half2_rn(v.x, v.y);
        __half2 h1 = __floats2half2_rn(v.z, v.w);
        xh[i] = make_uint2(*(unsigned*)&h0, *(unsigned*)&h1);
    }
}

// ---------------- tensor-core GEMM ----------------
// Ch[N,128](fp16) = dinv[row] * ((A1 (+A2)) @ half(W))
// CTA 128x128, K=128 in 2 chunks of 64. 8 warps: warpM=wid&3 (32 rows), warpN=wid>>2 (64 cols).
#define GP 72    // sA pitch (halves)
#define BP 136   // sB pitch (halves)

__device__ __forceinline__ unsigned cvta_sh(const void* p) {
    return (unsigned)__cvta_generic_to_shared(p);
}
__device__ __forceinline__ void ldm_x4(unsigned* r, unsigned addr) {
    asm volatile("ldmatrix.sync.aligned.m8n8.x4.shared.b16 {%0,%1,%2,%3}, [%4];"
                 : "=r"(r[0]), "=r"(r[1]), "=r"(r[2]), "=r"(r[3]) : "r"(addr));
}
__device__ __forceinline__ void ldm_x4_t(unsigned* r, unsigned addr) {
    asm volatile("ldmatrix.sync.aligned.m8n8.x4.trans.shared.b16 {%0,%1,%2,%3}, [%4];"
                 : "=r"(r[0]), "=r"(r[1]), "=r"(r[2]), "=r"(r[3]) : "r"(addr));
}
__device__ __forceinline__ void mma16816(float* c, const unsigned* a,
                                         unsigned b0, unsigned b1) {
    asm volatile(
        "mma.sync.aligned.m16n8k16.row.col.f32.f16.f16.f32 "
        "{%0,%1,%2,%3}, {%4,%5,%6,%7}, {%8,%9}, {%0,%1,%2,%3};"
        : "+f"(c[0]), "+f"(c[1]), "+f"(c[2]), "+f"(c[3])
        : "r"(a[0]), "r"(a[1]), "r"(a[2]), "r"(a[3]), "r"(b0), "r"(b1));
}

__global__ __launch_bounds__(256, 1) void gemm_kernel(
    const __half* __restrict__ A1, const __half* __restrict__ A2, int hasB,
    const float* __restrict__ W, __half* __restrict__ Ch) {
    __shared__ __half sA[128 * GP];
    __shared__ __half sB[64 * BP];

    int tid = threadIdx.x;
    int lane = tid & 31, wid = tid >> 5;
    int warpM = wid & 3, warpN = wid >> 2;
    int rowBase = blockIdx.x * 128;

    float c[2][8][4];
#pragma unroll
    for (int mi = 0; mi < 2; mi++)
#pragma unroll
        for (int ni = 0; ni < 8; ni++)
#pragma unroll
            for (int j = 0; j < 4; j++) c[mi][ni][j] = 0.f;

    for (int k0 = 0; k0 < 128; k0 += 64) {
        // load A chunk: 128 rows x 64 halves
#pragma unroll
        for (int i = 0; i < 4; i++) {
            int idx = i * 256 + tid;
            int row = idx >> 3, c8 = idx & 7;
            int grow = rowBase + row;
            uint4 v = make_uint4(0, 0, 0, 0);
            if (grow < NN) {
                v = *(const uint4*)(A1 + (long)grow * 128 + k0 + c8 * 8);
                if (hasB) {
                    uint4 u = *(const uint4*)(A2 + (long)grow * 128 + k0 + c8 * 8);
                    __half2* vh = (__half2*)&v;
                    __half2* uh = (__half2*)&u;
                    vh[0] = __hadd2(vh[0], uh[0]);
                    vh[1] = __hadd2(vh[1], uh[1]);
                    vh[2] = __hadd2(vh[2], uh[2]);
                    vh[3] = __hadd2(vh[3], uh[3]);
                }
            }
            *(uint4*)&sA[row * GP + c8 * 8] = v;
        }
        // load W chunk: 64 k-rows x 128 cols fp32 -> fp16
#pragma unroll
        for (int i = 0; i < 8; i++) {
            int idx = i * 256 + tid;
            int row = idx >> 5, c4 = idx & 31;
            float4 w = *(const float4*)(W + (long)(k0 + row) * 128 + c4 * 4);
            __half2 h0 = __floats2half2_rn(w.x, w.y);
            __half2 h1 = __floats2half2_rn(w.z, w.w);
            uint2 p = make_uint2(*(unsigned*)&h0, *(unsigned*)&h1);
            *(uint2*)&sB[row * BP + c4 * 4] = p;
        }
        __syncthreads();

#pragma unroll
        for (int kk = 0; kk < 4; kk++) {
            unsigned a[2][4];
#pragma unroll
            for (int mi = 0; mi < 2; mi++) {
                unsigned addr = cvta_sh(&sA[(warpM * 32 + mi * 16 + (lane & 15)) * GP
                                            + kk * 16 + (lane >> 4) * 8]);
                ldm_x4(a[mi], addr);
            }
            unsigned b[4][4];
#pragma unroll
            for (int nj = 0; nj < 4; nj++) {
                unsigned addr = cvta_sh(&sB[(kk * 16 + (lane & 15)) * BP
                                            + warpN * 64 + nj * 16 + (lane >> 4) * 8]);
                ldm_x4_t(b[nj], addr);
            }
#pragma unroll
            for (int mi = 0; mi < 2; mi++)
#pragma unroll
                for (int ni = 0; ni < 8; ni++) {
                    unsigned b0 = b[ni >> 1][(ni & 1) * 2];
                    unsigned b1 = b[ni >> 1][(ni & 1) * 2 + 1];
                    mma16816(c[mi][ni], a[mi], b0, b1);
                }
        }
        __syncthreads();
    }

    // epilogue: scale by dinv[row], store fp16
    int gID = lane >> 2, tig = lane & 3;
#pragma unroll
    for (int mi = 0; mi < 2; mi++) {
        int r0 = rowBase + warpM * 32 + mi * 16 + gID;
        int r1 = r0 + 8;
        float d0 = (r0 < NN) ? g_dinv[r0] : 0.f;
        float d1 = (r1 < NN) ? g_dinv[r1] : 0.f;
#pragma unroll
        for (int ni = 0; ni < 8; ni++) {
            int col = warpN * 64 + ni * 8 + tig * 2;
            if (r0 < NN) {
                __half2 h = __floats2half2_rn(d0 * c[mi][ni][0], d0 * c[mi][ni][1]);
                *(unsigned*)(Ch + (long)r0 * 128 + col) = *(unsigned*)&h;
            }
            if (r1 < NN) {
                __half2 h = __floats2half2_rn(d1 * c[mi][ni][2], d1 * c[mi][ni][3]);
                *(unsigned*)(Ch + (long)r1 * 128 + col) = *(unsigned*)&h;
            }
        }
    }
}

// ---------------- aggregation ----------------
__device__ __forceinline__ void add_h(float4& acc, uint2 v) {
    __half2 h0 = *(__half2*)&v.x;
    __half2 h1 = *(__half2*)&v.y;
    float2 f0 = __half22float2(h0);
    float2 f1 = __half22float2(h1);
    acc.x += f0.x; acc.y += f0.y; acc.z += f1.x; acc.w += f1.y;
}

__global__ __launch_bounds__(256) void agg_kernel(
    const uint2* __restrict__ tmp, const float* __restrict__ bias,
    uint2* __restrict__ out) {
    int lane = threadIdx.x & 31;
    int node = (blockIdx.x * blockDim.x + threadIdx.x) >> 5;
    if (node >= NN) return;

    int beg = g_rowptr[node];
    int end = g_rowptr[node + 1];

    float4 acc = make_float4(0.f, 0.f, 0.f, 0.f);
    int e = beg;
    for (; e + 8 <= end; e += 8) {
        uint2 v0 = tmp[(long)g_col[e    ] * 32 + lane];
        uint2 v1 = tmp[(long)g_col[e + 1] * 32 + lane];
        uint2 v2 = tmp[(long)g_col[e + 2] * 32 + lane];
        uint2 v3 = tmp[(long)g_col[e + 3] * 32 + lane];
        uint2 v4 = tmp[(long)g_col[e + 4] * 32 + lane];
        uint2 v5 = tmp[(long)g_col[e + 5] * 32 + lane];
        uint2 v6 = tmp[(long)g_col[e + 6] * 32 + lane];
        uint2 v7 = tmp[(long)g_col[e + 7] * 32 + lane];
        add_h(acc, v0); add_h(acc, v1); add_h(acc, v2); add_h(acc, v3);
        add_h(acc, v4); add_h(acc, v5); add_h(acc, v6); add_h(acc, v7);
    }
    for (; e < end; e++) {
        uint2 v0 = tmp[(long)g_col[e] * 32 + lane];
        add_h(acc, v0);
    }
    uint2 vs = tmp[(long)node * 32 + lane];
    add_h(acc, vs);

    float di = g_dinv[node];
    float4 b = ((const float4*)bias)[lane];
    float ox = fmaxf(fmaf(di, acc.x, b.x), 0.f);
    float oy = fmaxf(fmaf(di, acc.y, b.y), 0.f);
    float oz = fmaxf(fmaf(di, acc.z, b.z), 0.f);
    float ow = fmaxf(fmaf(di, acc.w, b.w), 0.f);
    __half2 h0 = __floats2half2_rn(ox, oy);
    __half2 h1 = __floats2half2_rn(oz, ow);
    out[(long)node * 32 + lane] = make_uint2(*(unsigned*)&h0, *(unsigned*)&h1);
}

// ---------------- pooling over sorted batch ids ----------------
#define POOL_NODES 256
__global__ void pool_kernel(const __half* __restrict__ cur,
                            const void* __restrict__ batch) {
    int is64 = g_b64;
    int f = threadIdx.x;
    int start = blockIdx.x * POOL_NODES;
    if (start >= NN) return;
    int endn = start + POOL_NODES;
    if (endn > NN) endn = NN;

    int curg = load_idx(batch, start, is64);
    float acc = 0.f;
    int cnt = 0;
    for (int nd = start; nd < endn; nd++) {
        int gg = load_idx(batch, nd, is64);
        if (gg != curg) {
            atomicAdd(&g_gsum[curg * HID + f], acc);
            if (f == 0) atomicAdd(&g_gcnt[curg], cnt);
            acc = 0.f; cnt = 0; curg = gg;
        }
        acc += __half2float(cur[(long)nd * HID + f]);
        cnt++;
    }
    atomicAdd(&g_gsum[curg * HID + f], acc);
    if (f == 0) atomicAdd(&g_gcnt[curg], cnt);
}

// ---------------- mean + linear head + outputs ----------------
__global__ void final_kernel(const float* __restrict__ Wl,
                             const float* __restrict__ bl,
                             float* __restrict__ out) {
    __shared__ float sm[HID];
    int g = blockIdx.x;
    int f = threadIdx.x;
    float c = (float)g_gcnt[g];
    c = fmaxf(c, 1.f);
    float m = g_gsum[g * HID + f] / c;
    sm[f] = m;
    out[NGRAPH * NCLS + (long)g * HID + f] = m;
    __syncthreads();
    if (f < NCLS) {
        float y = bl[f];
#pragma unroll 8
        for (int k = 0; k < HID; k++) y = fmaf(sm[k], Wl[k * NCLS + f], y);
        out[g * NCLS + f] = y;
    }
}

// ---------------- host ----------------
extern "C" void kernel_launch(void* const* d_in, const int* in_sizes, int n_in,
                              void* d_out, int out_size) {
    const float* x     = (const float*)d_in[0];
    const void*  ei    = d_in[1];
    const void*  batch = d_in[2];
    const float* W_in  = (const float*)d_in[3];
    const float* b_in  = (const float*)d_in[4];
    const float* W_hid = (const float*)d_in[5];
    const float* b_hid = (const float*)d_in[6];
    const float* W_lin = (const float*)d_in[7];
    const float* b_lin = (const float*)d_in[8];
    float* out = (float*)d_out;

    __half *tmph, *xh, *hb0, *hb1, *hb2;
    cudaGetSymbolAddress((void**)&tmph, g_tmph);
    cudaGetSymbolAddress((void**)&xh,  g_xh);
    cudaGetSymbolAddress((void**)&hb0, g_hb0);
    cudaGetSymbolAddress((void**)&hb1, g_hb1);
    cudaGetSymbolAddress((void**)&hb2, g_hb2);

    detect_kernel<<<1, 32>>>((const int*)ei, (const int*)batch);
    zero_kernel<<<(NGRAPH * HID + 255) / 256, 256>>>();
    hist_kernel<<<1024, 256>>>(ei);
    scan1_kernel<<<SCAN_NB, SCAN_TPB>>>();
    scan2_kernel<<<1, SCAN_TPB>>>();
    scan3_kernel<<<SCAN_NB, SCAN_TPB>>>();
    fill_kernel<<<1024, 256>>>(ei);
    cvt_kernel<<<(NN * 32 + 255) / 256, 256>>>((const float4*)x, (uint2*)xh);

    const int GEMM_GRID = (NN + 127) / 128;
    const int AGG_GRID  = (NN * 32 + 255) / 256;

    // input layer
    gemm_kernel<<<GEMM_GRID, 256>>>(xh, xh, 0, W_in, tmph);
    agg_kernel<<<AGG_GRID, 256>>>((const uint2*)tmph, b_in, (uint2*)hb0);
    // layer 0
    gemm_kernel<<<GEMM_GRID, 256>>>(hb0, hb0, 0, W_hid + 0 * 16384, tmph);
    agg_kernel<<<AGG_GRID, 256>>>((const uint2*)tmph, b_hid + 0 * HID, (uint2*)hb1);
    // layer 1
    gemm_kernel<<<GEMM_GRID, 256>>>(hb1, hb0, 1, W_hid + 1 * 16384, tmph);
    agg_kernel<<<AGG_GRID, 256>>>((const uint2*)tmph, b_hid + 1 * HID, (uint2*)hb2);
    // layer 2
    gemm_kernel<<<GEMM_GRID, 256>>>(hb2, hb1, 1, W_hid + 2 * 16384, tmph);
    agg_kernel<<<AGG_GRID, 256>>>((const uint2*)tmph, b_hid + 2 * HID, (uint2*)hb0);
    // layer 3
    gemm_kernel<<<GEMM_GRID, 256>>>(hb0, hb2, 1, W_hid + 3 * 16384, tmph);
    agg_kernel<<<AGG_GRID, 256>>>((const uint2*)tmph, b_hid + 3 * HID, (uint2*)hb1);

    pool_kernel<<<(NN + POOL_NODES - 1) / POOL_NODES, 128>>>(hb1, batch);
    final_kernel<<<NGRAPH, HID>>>(W_lin, b_lin, out);
}